// round 7
// baseline (speedup 1.0000x reference)
#include <cuda_runtime.h>

// ---------------------------------------------------------------------------
// TrackCrop: input [32, 512, 512, 3] f32.
// Both kernels are memory-INSTRUCTION-issue bound (LSU / ALU floors), so this
// revision minimizes instructions per element:
//  reduce: per 12-element row-chunk, one fmin-tree + 2 predicated adds
//          (exact: a running global min triggers a full exact recompute for
//          the astronomically-rare thread that saw a zero).
//  crop:   5x LDG.128 + register realign + 4x STG.128 per 16 floats
//          (src misalignment p = row_start & 3 is uniform per batch).
// ---------------------------------------------------------------------------

#define NBATCH 32
#define SY 512
#define SX 512
#define NC 3
#define ROW_FLOATS (SX * NC)        // 1536
#define ROW_F4 (ROW_FLOATS / 4)     // 384
#define CROP 256
#define OUT_ROW_FLOATS (CROP * NC)  // 768

#define RB 32                       // rows per reduce block
#define RBLOCKS_PER_BATCH (SY / RB) // 16

#define CROWS 8                         // rows per crop block
#define CTHREADS 384                    // 48 threads/row * 8 rows
#define CBLOCKS_PER_BATCH (CROP / CROWS)// 32

#define CNT_ONE (1 << 20)
#define SX_MASK (CNT_ONE - 1)

__device__ int  g_cnt[NBATCH];   // zero at load; returned to 0 every run
__device__ int  g_sx[NBATCH];
__device__ int  g_sy[NBATCH];
__device__ int  g_tick[NBATCH];
__device__ int2 g_HW[NBATCH];    // (H, W) crop origin per batch

__global__ __launch_bounds__(128) void reduce_kernel(const float* __restrict__ in) {
    const int t  = threadIdx.x;             // 0..127
    const int b  = blockIdx.y;              // 0..31
    const int y0 = blockIdx.x * RB;         // 0,32,...,480

    // Per-thread fast-path constant: sum of the 12 x-coords + 12 counts.
    int xsum = 0;
    #pragma unroll
    for (int i = 0; i < 3; i++) {
        const int j = 4 * (t + i * 128);
        #pragma unroll
        for (int k = 0; k < 4; k++)
            xsum += (j + k) / 3;
    }
    const int W12 = xsum + 12 * CNT_ONE;

    const float4* __restrict__ base =
        (const float4*)(in + ((size_t)b * SY + y0) * ROW_FLOATS);

    int   acc = 0;          // packed: sx [0,20), cnt [20,..)
    int   syf = 0;
    int   y12 = 12 * y0;
    float gm  = 1.0f;       // running min over all rows; ==0 -> exact redo
    #pragma unroll 4
    for (int r = 0; r < RB; r++) {
        const float4* __restrict__ row = base + (size_t)r * ROW_F4;
        const float4 a = row[t];
        const float4 c = row[t + 128];
        const float4 d = row[t + 256];

        // min(|v|) over 12 values; ==0 iff some element is +/-0 (any sign safe).
        const float m =
            fminf(fminf(fminf(fminf(fabsf(a.x), fabsf(a.y)),
                              fminf(fabsf(a.z), fabsf(a.w))),
                        fminf(fminf(fabsf(c.x), fabsf(c.y)),
                              fminf(fabsf(c.z), fabsf(c.w)))),
                  fminf(fminf(fabsf(d.x), fabsf(d.y)),
                        fminf(fabsf(d.z), fabsf(d.w))));
        gm = fminf(gm, m);
        const bool ok = (m != 0.0f);
        acc += ok ? W12 : 0;
        syf += ok ? y12 : 0;
        y12 += 12;
    }

    int cnt = acc >> 20;
    int sx  = acc & SX_MASK;
    int sy  = syf;

    if (gm == 0.0f) {
        // Rare exact path: at least one element of this thread's strip was
        // zero. Recompute the whole strip exactly (reloads hit cache).
        cnt = 0; sx = 0; sy = 0;
        for (int r = 0; r < RB; r++) {
            const float4* __restrict__ row = base + (size_t)r * ROW_F4;
            int rc = 0;
            #pragma unroll
            for (int i = 0; i < 3; i++) {
                const float4 v = row[t + i * 128];
                const int j = 4 * (t + i * 128);
                const float e[4] = {v.x, v.y, v.z, v.w};
                #pragma unroll
                for (int k = 0; k < 4; k++)
                    if (e[k] != 0.0f) { rc++; sx += (j + k) / 3; }
            }
            cnt += rc;
            sy  += (y0 + r) * rc;
        }
    }

    // warp reduce
    #pragma unroll
    for (int o = 16; o > 0; o >>= 1) {
        cnt += __shfl_down_sync(0xFFFFFFFFu, cnt, o);
        sx  += __shfl_down_sync(0xFFFFFFFFu, sx,  o);
        sy  += __shfl_down_sync(0xFFFFFFFFu, sy,  o);
    }

    __shared__ int s_cnt, s_sx, s_sy;
    if (t == 0) { s_cnt = 0; s_sx = 0; s_sy = 0; }
    __syncthreads();
    if ((t & 31) == 0) {
        atomicAdd(&s_cnt, cnt);
        atomicAdd(&s_sx,  sx);
        atomicAdd(&s_sy,  sy);
    }
    __syncthreads();

    if (t == 0) {
        atomicAdd(&g_cnt[b], s_cnt);
        atomicAdd(&g_sx[b],  s_sx);
        atomicAdd(&g_sy[b],  s_sy);
        __threadfence();
        if (atomicAdd(&g_tick[b], 1) == RBLOCKS_PER_BATCH - 1) {
            // Last block for this batch: read+reset (scratch back to 0 for
            // the next graph replay), publish crop origin.
            const int c  = atomicExch(&g_cnt[b], 0);
            const int xs = atomicExch(&g_sx[b],  0);
            const int ys = atomicExch(&g_sy[b],  0);
            atomicExch(&g_tick[b], 0);
            // Reference numerics: int32->f32 RN, IEEE f32 divide, trunc cast.
            const float fc = __int2float_rn(c);
            const int xcm = (int)__fdiv_rn(__int2float_rn(xs), fc);
            const int ycm = (int)__fdiv_rn(__int2float_rn(ys), fc);
            int2 hw;
            hw.x = min(max(ycm - CROP / 2, 0), SY - 1 - CROP);  // H
            hw.y = min(max(xcm - CROP / 2, 0), SX - 1 - CROP);  // W
            g_HW[b] = hw;
        }
    }
}

// 384 threads = 48 threads/row x 8 rows. Each thread moves 16 floats with
// 5 aligned LDG.128 + register realign (switch on uniform p) + 4 STG.128.
__global__ __launch_bounds__(CTHREADS, 1) void crop_kernel(const float* __restrict__ in,
                                                           float* __restrict__ out) {
    const int t   = threadIdx.x;          // 0..383
    const int b   = blockIdx.y;           // batch
    const int row = blockIdx.x * CROWS + (t / 48);  // output row 0..255
    const int c   = t % 48;               // 16-float chunk within the row

    const int2 hw = g_HW[b];              // (H, W)

    const size_t S = (size_t)b * (SY * SX * NC)
                   + ((size_t)(hw.x + row) * SX + hw.y) * NC;  // row start (floats)
    const int p = (int)(S & 3);           // uniform per batch

    const float4* __restrict__ src4 =
        (const float4*)(in + (S - p)) + (size_t)c * 4;
    const float4 f0 = src4[0];
    const float4 f1 = src4[1];
    const float4 f2 = src4[2];
    const float4 f3 = src4[3];
    const float4 f4v = src4[4];           // 16B overread, stays in-buffer

    float4 o0, o1, o2, o3;
    switch (p) {
    case 0:
        o0 = f0; o1 = f1; o2 = f2; o3 = f3;
        break;
    case 1:
        o0 = make_float4(f0.y, f0.z, f0.w, f1.x);
        o1 = make_float4(f1.y, f1.z, f1.w, f2.x);
        o2 = make_float4(f2.y, f2.z, f2.w, f3.x);
        o3 = make_float4(f3.y, f3.z, f3.w, f4v.x);
        break;
    case 2:
        o0 = make_float4(f0.z, f0.w, f1.x, f1.y);
        o1 = make_float4(f1.z, f1.w, f2.x, f2.y);
        o2 = make_float4(f2.z, f2.w, f3.x, f3.y);
        o3 = make_float4(f3.z, f3.w, f4v.x, f4v.y);
        break;
    default: // 3
        o0 = make_float4(f0.w, f1.x, f1.y, f1.z);
        o1 = make_float4(f1.w, f2.x, f2.y, f2.z);
        o2 = make_float4(f2.w, f3.x, f3.y, f3.z);
        o3 = make_float4(f3.w, f4v.x, f4v.y, f4v.z);
        break;
    }

    float4* __restrict__ dst =
        (float4*)(out + ((size_t)b * CROP + row) * OUT_ROW_FLOATS) + (size_t)c * 4;
    dst[0] = o0;
    dst[1] = o1;
    dst[2] = o2;
    dst[3] = o3;
}

extern "C" void kernel_launch(void* const* d_in, const int* in_sizes, int n_in,
                              void* d_out, int out_size) {
    const float* in = (const float*)d_in[0];
    float* out = (float*)d_out;

    reduce_kernel<<<dim3(RBLOCKS_PER_BATCH, NBATCH), 128>>>(in);
    crop_kernel<<<dim3(CBLOCKS_PER_BATCH, NBATCH), CTHREADS>>>(in, out);
}

// round 8
// speedup vs baseline: 1.1528x; 1.1528x over previous
#include <cuda_runtime.h>

// ---------------------------------------------------------------------------
// TrackCrop: input [32, 512, 512, 3] f32 -> per-batch centroid -> 256x256 crop.
// SINGLE fused kernel: grid (16,32) x 128 threads, all blocks resident.
//  Phase 1: packed-accumulator reduce (best measured variant).
//           Last block per batch (ticket) computes crop origin, publishes
//           g_HW[b], raises g_flag[b].
//  Phase 2: the same 16 blocks of batch b spin on g_flag[b], then copy 16
//           crop rows each (coalesced scalar). Crop overlaps other batches'
//           reduce and reads input while L2-hot.
//  All scratch (cnt/sx/sy/tick/flag/tick2) is returned to 0 -> graph-replay
//  deterministic, alloc-free.
// ---------------------------------------------------------------------------

#define NBATCH 32
#define SY 512
#define SX 512
#define NC 3
#define ROW_FLOATS (SX * NC)        // 1536
#define ROW_F4 (ROW_FLOATS / 4)     // 384
#define CROP 256
#define OUT_ROW_FLOATS (CROP * NC)  // 768

#define RB 32                       // rows per block (reduce)
#define BLOCKS_PER_BATCH (SY / RB)  // 16
#define CROWS (CROP / BLOCKS_PER_BATCH) // 16 crop rows per block

#define CNT_ONE (1 << 20)           // cnt above bit 20; sx below
#define SX_MASK (CNT_ONE - 1)

__device__ int  g_cnt[NBATCH];   // zero at load; returned to 0 every run
__device__ int  g_sx[NBATCH];
__device__ int  g_sy[NBATCH];
__device__ int  g_tick[NBATCH];
__device__ int  g_flag[NBATCH];
__device__ int  g_tick2[NBATCH];
__device__ int2 g_HW[NBATCH];    // (H, W) crop origin per batch

__global__ __launch_bounds__(128) void fused_kernel(const float* __restrict__ in,
                                                    float* __restrict__ out) {
    const int t  = threadIdx.x;             // 0..127
    const int b  = blockIdx.y;              // 0..31
    const int bx = blockIdx.x;              // 0..15
    const int y0 = bx * RB;

    // ---------------- Phase 1: reduce (packed accumulator) ----------------
    // Per-lane packed weights: x-coordinate + CNT_ONE, hoisted.
    int w[12];
    #pragma unroll
    for (int i = 0; i < 3; i++) {
        const int j = 4 * (t + i * 128);
        #pragma unroll
        for (int k = 0; k < 4; k++)
            w[i * 4 + k] = (j + k) / 3 + CNT_ONE;
    }

    const float4* __restrict__ base =
        (const float4*)(in + ((size_t)b * SY + y0) * ROW_FLOATS);

    int accT = 0;   // packed: sx [0,20), cnt [20,..)
    int sy   = 0;
    #pragma unroll 4
    for (int r = 0; r < RB; r++) {
        const float4* __restrict__ row = base + (size_t)r * ROW_F4;
        const float4 a = row[t];
        const float4 c = row[t + 128];
        const float4 d = row[t + 256];

        int acc = 0;
        if (a.x != 0.0f) acc += w[0];
        if (a.y != 0.0f) acc += w[1];
        if (a.z != 0.0f) acc += w[2];
        if (a.w != 0.0f) acc += w[3];
        if (c.x != 0.0f) acc += w[4];
        if (c.y != 0.0f) acc += w[5];
        if (c.z != 0.0f) acc += w[6];
        if (c.w != 0.0f) acc += w[7];
        if (d.x != 0.0f) acc += w[8];
        if (d.y != 0.0f) acc += w[9];
        if (d.z != 0.0f) acc += w[10];
        if (d.w != 0.0f) acc += w[11];

        accT += acc;
        sy   += (y0 + r) * (acc >> 20);
    }

    int cnt = accT >> 20;
    int sx  = accT & SX_MASK;

    #pragma unroll
    for (int o = 16; o > 0; o >>= 1) {
        cnt += __shfl_down_sync(0xFFFFFFFFu, cnt, o);
        sx  += __shfl_down_sync(0xFFFFFFFFu, sx,  o);
        sy  += __shfl_down_sync(0xFFFFFFFFu, sy,  o);
    }

    __shared__ int s_cnt, s_sx, s_sy;
    if (t == 0) { s_cnt = 0; s_sx = 0; s_sy = 0; }
    __syncthreads();
    if ((t & 31) == 0) {
        atomicAdd(&s_cnt, cnt);
        atomicAdd(&s_sx,  sx);
        atomicAdd(&s_sy,  sy);
    }
    __syncthreads();

    if (t == 0) {
        atomicAdd(&g_cnt[b], s_cnt);
        atomicAdd(&g_sx[b],  s_sx);
        atomicAdd(&g_sy[b],  s_sy);
        __threadfence();
        if (atomicAdd(&g_tick[b], 1) == BLOCKS_PER_BATCH - 1) {
            // Finalizer: read+reset scratch, publish origin, raise flag.
            const int c  = atomicExch(&g_cnt[b], 0);
            const int xs = atomicExch(&g_sx[b],  0);
            const int ys = atomicExch(&g_sy[b],  0);
            atomicExch(&g_tick[b], 0);
            // Reference numerics: int32->f32 RN, IEEE f32 divide, trunc cast.
            const float fc = __int2float_rn(c);
            const int xcm = (int)__fdiv_rn(__int2float_rn(xs), fc);
            const int ycm = (int)__fdiv_rn(__int2float_rn(ys), fc);
            int2 hw;
            hw.x = min(max(ycm - CROP / 2, 0), SY - 1 - CROP);  // H
            hw.y = min(max(xcm - CROP / 2, 0), SX - 1 - CROP);  // W
            g_HW[b] = hw;
            __threadfence();
            atomicExch(&g_flag[b], 1);
        }
    }

    // ---------------- Spin until this batch's origin is published ----------
    if (t == 0) {
        while (atomicAdd(&g_flag[b], 0) == 0) { }
    }
    __syncthreads();

    // g_HW[b] written before the flag (fenced); read via volatile to skip L1.
    const int hH = ((volatile int*)&g_HW[b].x)[0];
    const int hW = ((volatile int*)&g_HW[b].y)[0];

    // ---------------- Phase 2: crop 16 rows per block ----------------------
    const float* __restrict__ inb  = in  + (size_t)b * (SY * SX * NC);
    float* __restrict__       outb = out + (size_t)b * (CROP * OUT_ROW_FLOATS);

    #pragma unroll 2
    for (int rr = 0; rr < CROWS; rr++) {
        const int row = bx * CROWS + rr;                 // output row
        const float* __restrict__ src =
            inb + ((size_t)(hH + row) * SX + hW) * NC + t;
        float* __restrict__ dst =
            outb + (size_t)row * OUT_ROW_FLOATS + t;
        float v[6];
        #pragma unroll
        for (int k = 0; k < 6; k++)
            v[k] = src[k * 128];
        #pragma unroll
        for (int k = 0; k < 6; k++)
            dst[k * 128] = v[k];
    }

    // ---------------- Reset flag for next graph replay ----------------------
    __syncthreads();
    if (t == 0) {
        if (atomicAdd(&g_tick2[b], 1) == BLOCKS_PER_BATCH - 1) {
            atomicExch(&g_tick2[b], 0);
            atomicExch(&g_flag[b],  0);
        }
    }
}

extern "C" void kernel_launch(void* const* d_in, const int* in_sizes, int n_in,
                              void* d_out, int out_size) {
    const float* in = (const float*)d_in[0];
    float* out = (float*)d_out;

    fused_kernel<<<dim3(BLOCKS_PER_BATCH, NBATCH), 128>>>(in, out);
}